// round 1
// baseline (speedup 1.0000x reference)
#include <cuda_runtime.h>
#include <math.h>

#define NN 50000
#define EE 600000
#define HH 128

// Scratch (alloc-free rule: __device__ globals)
__device__ __align__(16) float g_Pi[NN * HH];      // node_embs_i @ W_sem[0:128]
__device__ __align__(16) float g_Pj[NN * HH];      // node_embs_j @ W_sem[128:256]
__device__ __align__(16) float g_Wcomb[10 * HH];   // blockdiag(W_geo,W_geo) @ W_pair

__device__ __forceinline__ float sigmoidf_(float x) {
    return 1.0f / (1.0f + __expf(-x));
}

// ---------------------------------------------------------------------------
// Setup kernel 1: Wcomb[d][c] = sum_m W_geo[d%5][m] * W_pair[(d/5)*128 + m][c]
// grid: 10 blocks x 128 threads
// ---------------------------------------------------------------------------
__global__ void wcomb_kernel(const float* __restrict__ Wgeo,
                             const float* __restrict__ Wpair) {
    int c = threadIdx.x;          // 0..127
    int d = blockIdx.x;           // 0..9
    int dd = d % 5;
    const float* wp = Wpair + (d / 5) * 128 * HH;
    float acc = 0.0f;
#pragma unroll 4
    for (int m = 0; m < 128; m++)
        acc = fmaf(Wgeo[dd * HH + m], wp[m * HH + c], acc);
    g_Wcomb[d * HH + c] = acc;
}

// ---------------------------------------------------------------------------
// Setup kernel 2: P_i = embs_i @ W_sem[0:128,:], P_j = embs_j @ W_sem[128:256,:]
// 64-row tile per block, 256 threads, 8x4 register tile, both GEMMs fused.
// ---------------------------------------------------------------------------
__global__ __launch_bounds__(256, 1) void pk_kernel(const float* __restrict__ Ei,
                                                    const float* __restrict__ Ej,
                                                    const float* __restrict__ Wsem) {
    extern __shared__ float sm[];
    float* sWt = sm;                   // 128*128
    float* sWb = sWt + 128 * 128;      // 128*128
    float* sAi = sWb + 128 * 128;      // 64*128
    float* sAj = sAi + 64 * 128;       // 64*128

    int tid = threadIdx.x;
    for (int i = tid; i < 4096; i += 256) {
        ((float4*)sWt)[i] = ((const float4*)Wsem)[i];
        ((float4*)sWb)[i] = ((const float4*)(Wsem + 128 * HH))[i];
    }
    int base = blockIdx.x * 64;
    for (int i = tid; i < 2048; i += 256) {  // 64 rows * 32 float4
        int r = i >> 5;
        int c4 = i & 31;
        int row = base + r;
        float4 v = make_float4(0.f, 0.f, 0.f, 0.f);
        float4 w = make_float4(0.f, 0.f, 0.f, 0.f);
        if (row < NN) {
            v = ((const float4*)Ei)[row * 32 + c4];
            w = ((const float4*)Ej)[row * 32 + c4];
        }
        ((float4*)sAi)[i] = v;
        ((float4*)sAj)[i] = w;
    }
    __syncthreads();

    int rg = tid >> 5;
    int lane = tid & 31;
    int col = lane * 4;
    int rbase = rg * 8;
    float acc1[8][4];
    float acc2[8][4];
#pragma unroll
    for (int i = 0; i < 8; i++)
#pragma unroll
        for (int j = 0; j < 4; j++) { acc1[i][j] = 0.f; acc2[i][j] = 0.f; }

#pragma unroll 2
    for (int k = 0; k < 128; k += 2) {
        float4 wt0 = *(const float4*)&sWt[(k)     * HH + col];
        float4 wt1 = *(const float4*)&sWt[(k + 1) * HH + col];
        float4 wb0 = *(const float4*)&sWb[(k)     * HH + col];
        float4 wb1 = *(const float4*)&sWb[(k + 1) * HH + col];
#pragma unroll
        for (int i = 0; i < 8; i++) {
            float2 ai = *(const float2*)&sAi[(rbase + i) * HH + k];
            float2 aj = *(const float2*)&sAj[(rbase + i) * HH + k];
            acc1[i][0] = fmaf(ai.x, wt0.x, fmaf(ai.y, wt1.x, acc1[i][0]));
            acc1[i][1] = fmaf(ai.x, wt0.y, fmaf(ai.y, wt1.y, acc1[i][1]));
            acc1[i][2] = fmaf(ai.x, wt0.z, fmaf(ai.y, wt1.z, acc1[i][2]));
            acc1[i][3] = fmaf(ai.x, wt0.w, fmaf(ai.y, wt1.w, acc1[i][3]));
            acc2[i][0] = fmaf(aj.x, wb0.x, fmaf(aj.y, wb1.x, acc2[i][0]));
            acc2[i][1] = fmaf(aj.x, wb0.y, fmaf(aj.y, wb1.y, acc2[i][1]));
            acc2[i][2] = fmaf(aj.x, wb0.z, fmaf(aj.y, wb1.z, acc2[i][2]));
            acc2[i][3] = fmaf(aj.x, wb0.w, fmaf(aj.y, wb1.w, acc2[i][3]));
        }
    }
#pragma unroll
    for (int i = 0; i < 8; i++) {
        int row = base + rbase + i;
        if (row < NN) {
            *(float4*)&g_Pi[(size_t)row * HH + col] =
                make_float4(acc1[i][0], acc1[i][1], acc1[i][2], acc1[i][3]);
            *(float4*)&g_Pj[(size_t)row * HH + col] =
                make_float4(acc2[i][0], acc2[i][1], acc2[i][2], acc2[i][3]);
        }
    }
}

// ---------------------------------------------------------------------------
// Main fused kernel: 64 edges per block, 256 threads.
// Phase A: geometry + gate + LN  -> h, edge_attr staged in smem
// Phase B: h@W_gate, edge_attr@W_res (8x4 reg tile) + epilogue
// ---------------------------------------------------------------------------
__global__ __launch_bounds__(256, 1) void edge_kernel(
    const float* __restrict__ pos_i, const float* __restrict__ pos_j,
    const float* __restrict__ hd_i, const float* __restrict__ hd_j,
    const int* __restrict__ eidx, const float* __restrict__ edge_attr,
    const float* __restrict__ b_sem, const float* __restrict__ gamma,
    const float* __restrict__ beta, const float* __restrict__ Wgate,
    const float* __restrict__ Wres, float* __restrict__ out) {
    extern __shared__ float sm[];
    float* sWg = sm;                   // 16384
    float* sWr = sWg + 16384;          // 16384
    float* sAh = sWr + 16384;          // 8192
    float* sAe = sAh + 8192;           // 8192
    float* sWc = sAe + 8192;           // 1280

    int tid = threadIdx.x;
    int lane = tid & 31;
    int w = tid >> 5;
    int col = lane * 4;

    for (int i = tid; i < 4096; i += 256) {
        ((float4*)sWg)[i] = ((const float4*)Wgate)[i];
        ((float4*)sWr)[i] = ((const float4*)Wres)[i];
    }
    for (int i = tid; i < 320; i += 256)
        ((float4*)sWc)[i] = ((const float4*)g_Wcomb)[i];

    int base = blockIdx.x * 64;
    float4 bs = *(const float4*)&b_sem[col];
    float4 gm = *(const float4*)&gamma[col];
    float4 bt = *(const float4*)&beta[col];
    __syncthreads();

    // ---- Phase A: warp w handles edges base + w*8 .. base + w*8 + 7 ----
    for (int e8 = 0; e8 < 8; e8++) {
        int row = w * 8 + e8;
        int e = base + row;
        int src = eidx[e];
        int tgt = eidx[EE + e];

        float2 pi = ((const float2*)pos_i)[src];
        float2 pj = ((const float2*)pos_j)[tgt];
        float hi = hd_i[src];
        float hj = hd_j[tgt];
        float dx = pi.x - pj.x;
        float dy = pi.y - pj.y;

        float sj, cj;
        sincosf(hj, &sj, &cj);
        float x1 = dx * cj + dy * sj;
        float y1 = -dx * sj + dy * cj;
        float len1 = sqrtf(x1 * x1 + y1 * y1);
        float il1 = (len1 > 0.f) ? (1.f / len1) : 0.f;
        float ct1 = (len1 > 0.f) ? (x1 * il1) : 1.f;
        float st1 = y1 * il1;

        float si, ci;
        sincosf(hi, &si, &ci);
        float x2 = -dx * ci - dy * si;
        float y2 = dx * si - dy * ci;
        float len2 = sqrtf(x2 * x2 + y2 * y2);
        float il2 = (len2 > 0.f) ? (1.f / len2) : 0.f;
        float ct2 = (len2 > 0.f) ? (x2 * il2) : 1.f;
        float st2 = y2 * il2;

        float shd, chd;
        sincosf(hi - hj, &shd, &chd);

        float raw[10];
        raw[0] = len1; raw[1] = ct1; raw[2] = st1; raw[3] = chd; raw[4] = shd;
        raw[5] = len2; raw[6] = ct2; raw[7] = st2; raw[8] = chd; raw[9] = -shd;

        float4 g = make_float4(0.f, 0.f, 0.f, 0.f);
#pragma unroll
        for (int d = 0; d < 10; d++) {
            float4 wc = *(const float4*)&sWc[d * HH + col];
            g.x = fmaf(raw[d], wc.x, g.x);
            g.y = fmaf(raw[d], wc.y, g.y);
            g.z = fmaf(raw[d], wc.z, g.z);
            g.w = fmaf(raw[d], wc.w, g.w);
        }
        g.x = fmaxf(g.x, 0.f); g.y = fmaxf(g.y, 0.f);
        g.z = fmaxf(g.z, 0.f); g.w = fmaxf(g.w, 0.f);

        float4 Pi4 = *(const float4*)&g_Pi[(size_t)src * HH + col];
        float4 Pj4 = *(const float4*)&g_Pj[(size_t)tgt * HH + col];
        float4 ea4 = *(const float4*)&edge_attr[(size_t)e * HH + col];

        float4 pre;
        pre.x = fmaf(g.x, sigmoidf_(Pi4.x + Pj4.x + bs.x), ea4.x);
        pre.y = fmaf(g.y, sigmoidf_(Pi4.y + Pj4.y + bs.y), ea4.y);
        pre.z = fmaf(g.z, sigmoidf_(Pi4.z + Pj4.z + bs.z), ea4.z);
        pre.w = fmaf(g.w, sigmoidf_(Pi4.w + Pj4.w + bs.w), ea4.w);

        // LayerNorm over 128 (two-pass, warp shuffle)
        float ssum = pre.x + pre.y + pre.z + pre.w;
#pragma unroll
        for (int off = 16; off >= 1; off >>= 1)
            ssum += __shfl_xor_sync(0xffffffffu, ssum, off);
        float mu = ssum * (1.0f / 128.0f);
        float4 dvec;
        dvec.x = pre.x - mu; dvec.y = pre.y - mu;
        dvec.z = pre.z - mu; dvec.w = pre.w - mu;
        float sq = dvec.x * dvec.x + dvec.y * dvec.y + dvec.z * dvec.z + dvec.w * dvec.w;
#pragma unroll
        for (int off = 16; off >= 1; off >>= 1)
            sq += __shfl_xor_sync(0xffffffffu, sq, off);
        float rstd = rsqrtf(sq * (1.0f / 128.0f) + 1e-5f);

        float4 h4;
        h4.x = fmaf(dvec.x * rstd, gm.x, bt.x);
        h4.y = fmaf(dvec.y * rstd, gm.y, bt.y);
        h4.z = fmaf(dvec.z * rstd, gm.z, bt.z);
        h4.w = fmaf(dvec.w * rstd, gm.w, bt.w);

        *(float4*)&sAh[row * HH + col] = h4;
        *(float4*)&sAe[row * HH + col] = ea4;
    }
    __syncthreads();

    // ---- Phase B: GEMMs.  thread: rows w*8..w*8+7, cols lane*4..lane*4+3 ----
    int rbase = w * 8;
    float acc1[8][4];
    float acc2[8][4];
#pragma unroll
    for (int i = 0; i < 8; i++)
#pragma unroll
        for (int j = 0; j < 4; j++) { acc1[i][j] = 0.f; acc2[i][j] = 0.f; }

#pragma unroll 2
    for (int k = 0; k < 128; k += 2) {
        float4 wg0 = *(const float4*)&sWg[(k)     * HH + col];
        float4 wg1 = *(const float4*)&sWg[(k + 1) * HH + col];
        float4 wr0 = *(const float4*)&sWr[(k)     * HH + col];
        float4 wr1 = *(const float4*)&sWr[(k + 1) * HH + col];
#pragma unroll
        for (int i = 0; i < 8; i++) {
            float2 ah = *(const float2*)&sAh[(rbase + i) * HH + k];
            float2 ae = *(const float2*)&sAe[(rbase + i) * HH + k];
            acc1[i][0] = fmaf(ah.x, wg0.x, fmaf(ah.y, wg1.x, acc1[i][0]));
            acc1[i][1] = fmaf(ah.x, wg0.y, fmaf(ah.y, wg1.y, acc1[i][1]));
            acc1[i][2] = fmaf(ah.x, wg0.z, fmaf(ah.y, wg1.z, acc1[i][2]));
            acc1[i][3] = fmaf(ah.x, wg0.w, fmaf(ah.y, wg1.w, acc1[i][3]));
            acc2[i][0] = fmaf(ae.x, wr0.x, fmaf(ae.y, wr1.x, acc2[i][0]));
            acc2[i][1] = fmaf(ae.x, wr0.y, fmaf(ae.y, wr1.y, acc2[i][1]));
            acc2[i][2] = fmaf(ae.x, wr0.z, fmaf(ae.y, wr1.z, acc2[i][2]));
            acc2[i][3] = fmaf(ae.x, wr0.w, fmaf(ae.y, wr1.w, acc2[i][3]));
        }
    }

    // ---- Epilogue: out = h + sigmoid(h@Wg) * (ea@Wr - h) ----
#pragma unroll
    for (int i = 0; i < 8; i++) {
        int row = rbase + i;
        float4 h4 = *(const float4*)&sAh[row * HH + col];
        float4 o;
        o.x = fmaf(sigmoidf_(acc1[i][0]), acc2[i][0] - h4.x, h4.x);
        o.y = fmaf(sigmoidf_(acc1[i][1]), acc2[i][1] - h4.y, h4.y);
        o.z = fmaf(sigmoidf_(acc1[i][2]), acc2[i][2] - h4.z, h4.z);
        o.w = fmaf(sigmoidf_(acc1[i][3]), acc2[i][3] - h4.w, h4.w);
        *(float4*)&out[(size_t)(base + row) * HH + col] = o;
    }
}

// ---------------------------------------------------------------------------
extern "C" void kernel_launch(void* const* d_in, const int* in_sizes, int n_in,
                              void* d_out, int out_size) {
    const float* pos_i     = (const float*)d_in[0];
    const float* pos_j     = (const float*)d_in[1];
    const float* hd_i      = (const float*)d_in[2];
    const float* hd_j      = (const float*)d_in[3];
    const int*   eidx      = (const int*)d_in[4];
    const float* edge_attr = (const float*)d_in[5];
    const float* embs_i    = (const float*)d_in[6];
    const float* embs_j    = (const float*)d_in[7];
    const float* Wgeo      = (const float*)d_in[8];
    const float* Wpair     = (const float*)d_in[9];
    const float* Wsem      = (const float*)d_in[10];
    const float* bsem      = (const float*)d_in[11];
    const float* gamma     = (const float*)d_in[12];
    const float* beta      = (const float*)d_in[13];
    const float* Wgate     = (const float*)d_in[14];
    const float* Wres      = (const float*)d_in[15];

    cudaFuncSetAttribute(pk_kernel, cudaFuncAttributeMaxDynamicSharedMemorySize,
                         196608);
    cudaFuncSetAttribute(edge_kernel, cudaFuncAttributeMaxDynamicSharedMemorySize,
                         201728);

    wcomb_kernel<<<10, 128>>>(Wgeo, Wpair);
    pk_kernel<<<(NN + 63) / 64, 256, 196608>>>(embs_i, embs_j, Wsem);
    edge_kernel<<<EE / 64, 256, 201728>>>(pos_i, pos_j, hd_i, hd_j, eidx,
                                          edge_attr, bsem, gamma, beta, Wgate,
                                          Wres, (float*)d_out);
}

// round 3
// speedup vs baseline: 1.3272x; 1.3272x over previous
#include <cuda_runtime.h>
#include <math.h>

#define NN 50000
#define EE 600000
#define HH 128
#define SP 132   // padded smem row stride (floats) -> conflict-free mma frag loads

// Scratch (alloc-free rule: __device__ globals)
__device__ __align__(16) float g_Pi[NN * HH];      // node_embs_i @ W_sem[0:128]
__device__ __align__(16) float g_Pj[NN * HH];      // node_embs_j @ W_sem[128:256]
__device__ __align__(16) float g_Wcomb[10 * HH];   // blockdiag(W_geo,W_geo) @ W_pair

__device__ __forceinline__ float sigmoidf_(float x) {
    return 1.0f / (1.0f + __expf(-x));
}

__device__ __forceinline__ unsigned f2tf32(float x) {
    unsigned r;
    asm("cvt.rna.tf32.f32 %0, %1;" : "=r"(r) : "f"(x));
    return r;
}

__device__ __forceinline__ void mma_tf32(float* d, unsigned a0, unsigned a1,
                                         unsigned a2, unsigned a3,
                                         unsigned b0, unsigned b1) {
    asm volatile(
        "mma.sync.aligned.m16n8k8.row.col.f32.tf32.tf32.f32 "
        "{%0,%1,%2,%3}, {%4,%5,%6,%7}, {%8,%9}, {%0,%1,%2,%3};\n"
        : "+f"(d[0]), "+f"(d[1]), "+f"(d[2]), "+f"(d[3])
        : "r"(a0), "r"(a1), "r"(a2), "r"(a3), "r"(b0), "r"(b1));
}

// ---------------------------------------------------------------------------
// Setup kernel 1: Wcomb[d][c] = sum_m W_geo[d%5][m] * W_pair[(d/5)*128 + m][c]
// ---------------------------------------------------------------------------
__global__ void wcomb_kernel(const float* __restrict__ Wgeo,
                             const float* __restrict__ Wpair) {
    int c = threadIdx.x;
    int d = blockIdx.x;
    int dd = d % 5;
    const float* wp = Wpair + (d / 5) * 128 * HH;
    float acc = 0.0f;
#pragma unroll 16
    for (int m = 0; m < 128; m++)
        acc = fmaf(Wgeo[dd * HH + m], wp[m * HH + c], acc);
    g_Wcomb[d * HH + c] = acc;
}

// ---------------------------------------------------------------------------
// Setup kernel 2 (tf32 mma): P_i = embs_i @ W_sem[0:128], P_j = embs_j @ W_sem[128:]
// 64 rows per block, 256 threads. Warps 0-3 -> Pi, warps 4-7 -> Pj.
// ---------------------------------------------------------------------------
__global__ __launch_bounds__(256, 1) void pk_kernel(const float* __restrict__ Ei,
                                                    const float* __restrict__ Ej,
                                                    const float* __restrict__ Wsem) {
    extern __shared__ float sm[];
    float* sWt = sm;                 // 128*SP
    float* sWb = sWt + 128 * SP;     // 128*SP
    float* sAi = sWb + 128 * SP;     // 64*SP
    float* sAj = sAi + 64 * SP;      // 64*SP

    int tid = threadIdx.x;
    int lane = tid & 31;
    int w = tid >> 5;

    // stage weights (tf32-rounded) with padded stride
    for (int i = tid; i < 4096; i += 256) {
        int k = i >> 5, c4 = i & 31;
        float4 t = ((const float4*)Wsem)[i];
        float4 b = ((const float4*)(Wsem + 128 * HH))[i];
        uint4 tu = make_uint4(f2tf32(t.x), f2tf32(t.y), f2tf32(t.z), f2tf32(t.w));
        uint4 bu = make_uint4(f2tf32(b.x), f2tf32(b.y), f2tf32(b.z), f2tf32(b.w));
        *(uint4*)&sWt[k * SP + c4 * 4] = tu;
        *(uint4*)&sWb[k * SP + c4 * 4] = bu;
    }
    int base = blockIdx.x * 64;
    for (int i = tid; i < 2048; i += 256) {  // 64 rows * 32 float4
        int r = i >> 5, c4 = i & 31;
        int row = base + r;
        float4 v = make_float4(0.f, 0.f, 0.f, 0.f);
        float4 u = make_float4(0.f, 0.f, 0.f, 0.f);
        if (row < NN) {
            v = ((const float4*)Ei)[row * 32 + c4];
            u = ((const float4*)Ej)[row * 32 + c4];
        }
        *(uint4*)&sAi[r * SP + c4 * 4] =
            make_uint4(f2tf32(v.x), f2tf32(v.y), f2tf32(v.z), f2tf32(v.w));
        *(uint4*)&sAj[r * SP + c4 * 4] =
            make_uint4(f2tf32(u.x), f2tf32(u.y), f2tf32(u.z), f2tf32(u.w));
    }
    __syncthreads();

    const float* A = (w < 4) ? sAi : sAj;
    const float* W = (w < 4) ? sWt : sWb;
    int nb = (w & 3) * 32;
    int gid = lane >> 2, tig = lane & 3;

    float acc[4][4][4];
#pragma unroll
    for (int mt = 0; mt < 4; mt++)
#pragma unroll
        for (int nt = 0; nt < 4; nt++)
#pragma unroll
            for (int q = 0; q < 4; q++) acc[mt][nt][q] = 0.f;

#pragma unroll
    for (int kt = 0; kt < 16; kt++) {
        int k0 = kt * 8;
        unsigned b[4][2];
#pragma unroll
        for (int nt = 0; nt < 4; nt++) {
            int n = nb + nt * 8 + gid;
            b[nt][0] = __float_as_uint(W[(k0 + tig) * SP + n]);
            b[nt][1] = __float_as_uint(W[(k0 + 4 + tig) * SP + n]);
        }
#pragma unroll
        for (int mt = 0; mt < 4; mt++) {
            int m = mt * 16;
            unsigned a0 = __float_as_uint(A[(m + gid) * SP + k0 + tig]);
            unsigned a1 = __float_as_uint(A[(m + gid + 8) * SP + k0 + tig]);
            unsigned a2 = __float_as_uint(A[(m + gid) * SP + k0 + tig + 4]);
            unsigned a3 = __float_as_uint(A[(m + gid + 8) * SP + k0 + tig + 4]);
#pragma unroll
            for (int nt = 0; nt < 4; nt++)
                mma_tf32(acc[mt][nt], a0, a1, a2, a3, b[nt][0], b[nt][1]);
        }
    }

    float* G = (w < 4) ? g_Pi : g_Pj;
#pragma unroll
    for (int mt = 0; mt < 4; mt++)
#pragma unroll
        for (int nt = 0; nt < 4; nt++) {
            int row0 = base + mt * 16 + gid;
            int col = nb + nt * 8 + 2 * tig;
            if (row0 < NN)
                *(float2*)&G[(size_t)row0 * HH + col] =
                    make_float2(acc[mt][nt][0], acc[mt][nt][1]);
            int row1 = row0 + 8;
            if (row1 < NN)
                *(float2*)&G[(size_t)row1 * HH + col] =
                    make_float2(acc[mt][nt][2], acc[mt][nt][3]);
        }
}

// ---------------------------------------------------------------------------
// Main fused kernel: 64 edges / block, 256 threads.
// Phase A: geometry + gate + LN -> h (fp32) and ea staged in smem
// Phase B: tf32 mma GEMMs h@W_gate, ea@W_res; exchange via smem; epilogue.
// ---------------------------------------------------------------------------
__global__ __launch_bounds__(256, 1) void edge_kernel(
    const float* __restrict__ pos_i, const float* __restrict__ pos_j,
    const float* __restrict__ hd_i, const float* __restrict__ hd_j,
    const int* __restrict__ eidx, const float* __restrict__ edge_attr,
    const float* __restrict__ b_sem, const float* __restrict__ gamma,
    const float* __restrict__ beta, const float* __restrict__ Wgate,
    const float* __restrict__ Wres, float* __restrict__ out) {
    extern __shared__ float sm[];
    float* sWg = sm;                 // 128*SP (reused as sSig after GEMM)
    float* sWr = sWg + 128 * SP;     // 128*SP
    float* sAh = sWr + 128 * SP;     // 64*SP
    float* sAe = sAh + 64 * SP;      // 64*SP (reused as res buffer)
    float* sWc = sAe + 64 * SP;      // 10*128

    int tid = threadIdx.x;
    int lane = tid & 31;
    int w = tid >> 5;
    int col = lane * 4;

    for (int i = tid; i < 4096; i += 256) {
        int k = i >> 5, c4 = i & 31;
        float4 g = ((const float4*)Wgate)[i];
        float4 r = ((const float4*)Wres)[i];
        *(uint4*)&sWg[k * SP + c4 * 4] =
            make_uint4(f2tf32(g.x), f2tf32(g.y), f2tf32(g.z), f2tf32(g.w));
        *(uint4*)&sWr[k * SP + c4 * 4] =
            make_uint4(f2tf32(r.x), f2tf32(r.y), f2tf32(r.z), f2tf32(r.w));
    }
    for (int i = tid; i < 320; i += 256)
        ((float4*)sWc)[i] = ((const float4*)g_Wcomb)[i];

    int base = blockIdx.x * 64;
    float4 bs = *(const float4*)&b_sem[col];
    float4 gm = *(const float4*)&gamma[col];
    float4 bt = *(const float4*)&beta[col];
    __syncthreads();

    // ---- Phase A ----
#pragma unroll
    for (int e8 = 0; e8 < 8; e8++) {
        int row = w * 8 + e8;
        int e = base + row;
        int src = eidx[e];
        int tgt = eidx[EE + e];

        float2 pi = ((const float2*)pos_i)[src];
        float2 pj = ((const float2*)pos_j)[tgt];
        float hi = hd_i[src];
        float hj = hd_j[tgt];
        float dx = pi.x - pj.x;
        float dy = pi.y - pj.y;

        float sj, cj;
        __sincosf(hj, &sj, &cj);
        float x1 = dx * cj + dy * sj;
        float y1 = -dx * sj + dy * cj;
        float len1 = sqrtf(x1 * x1 + y1 * y1);
        float il1 = (len1 > 0.f) ? (1.f / len1) : 0.f;
        float ct1 = (len1 > 0.f) ? (x1 * il1) : 1.f;
        float st1 = y1 * il1;

        float si, ci;
        __sincosf(hi, &si, &ci);
        float x2 = -dx * ci - dy * si;
        float y2 = dx * si - dy * ci;
        float len2 = sqrtf(x2 * x2 + y2 * y2);
        float il2 = (len2 > 0.f) ? (1.f / len2) : 0.f;
        float ct2 = (len2 > 0.f) ? (x2 * il2) : 1.f;
        float st2 = y2 * il2;

        float shd, chd;
        __sincosf(hi - hj, &shd, &chd);

        float raw[10];
        raw[0] = len1; raw[1] = ct1; raw[2] = st1; raw[3] = chd; raw[4] = shd;
        raw[5] = len2; raw[6] = ct2; raw[7] = st2; raw[8] = chd; raw[9] = -shd;

        float4 g = make_float4(0.f, 0.f, 0.f, 0.f);
#pragma unroll
        for (int d = 0; d < 10; d++) {
            float4 wc = *(const float4*)&sWc[d * HH + col];
            g.x = fmaf(raw[d], wc.x, g.x);
            g.y = fmaf(raw[d], wc.y, g.y);
            g.z = fmaf(raw[d], wc.z, g.z);
            g.w = fmaf(raw[d], wc.w, g.w);
        }
        g.x = fmaxf(g.x, 0.f); g.y = fmaxf(g.y, 0.f);
        g.z = fmaxf(g.z, 0.f); g.w = fmaxf(g.w, 0.f);

        float4 Pi4 = *(const float4*)&g_Pi[(size_t)src * HH + col];
        float4 Pj4 = *(const float4*)&g_Pj[(size_t)tgt * HH + col];
        float4 ea4 = *(const float4*)&edge_attr[(size_t)e * HH + col];

        float4 pre;
        pre.x = fmaf(g.x, sigmoidf_(Pi4.x + Pj4.x + bs.x), ea4.x);
        pre.y = fmaf(g.y, sigmoidf_(Pi4.y + Pj4.y + bs.y), ea4.y);
        pre.z = fmaf(g.z, sigmoidf_(Pi4.z + Pj4.z + bs.z), ea4.z);
        pre.w = fmaf(g.w, sigmoidf_(Pi4.w + Pj4.w + bs.w), ea4.w);

        float ssum = pre.x + pre.y + pre.z + pre.w;
#pragma unroll
        for (int off = 16; off >= 1; off >>= 1)
            ssum += __shfl_xor_sync(0xffffffffu, ssum, off);
        float mu = ssum * (1.0f / 128.0f);
        float4 dv;
        dv.x = pre.x - mu; dv.y = pre.y - mu;
        dv.z = pre.z - mu; dv.w = pre.w - mu;
        float sq = dv.x * dv.x + dv.y * dv.y + dv.z * dv.z + dv.w * dv.w;
#pragma unroll
        for (int off = 16; off >= 1; off >>= 1)
            sq += __shfl_xor_sync(0xffffffffu, sq, off);
        float rstd = rsqrtf(sq * (1.0f / 128.0f) + 1e-5f);

        float4 h4;
        h4.x = fmaf(dv.x * rstd, gm.x, bt.x);
        h4.y = fmaf(dv.y * rstd, gm.y, bt.y);
        h4.z = fmaf(dv.z * rstd, gm.z, bt.z);
        h4.w = fmaf(dv.w * rstd, gm.w, bt.w);

        *(float4*)&sAh[row * SP + col] = h4;
        *(float4*)&sAe[row * SP + col] = ea4;
    }
    __syncthreads();

    // ---- Phase B: warps 0-3: gate = h@Wg ; warps 4-7: res = ea@Wr ----
    const float* A = (w < 4) ? sAh : sAe;
    const float* W = (w < 4) ? sWg : sWr;
    int nb = (w & 3) * 32;
    int gid = lane >> 2, tig = lane & 3;

    float acc[4][4][4];
#pragma unroll
    for (int mt = 0; mt < 4; mt++)
#pragma unroll
        for (int nt = 0; nt < 4; nt++)
#pragma unroll
            for (int q = 0; q < 4; q++) acc[mt][nt][q] = 0.f;

#pragma unroll
    for (int kt = 0; kt < 16; kt++) {
        int k0 = kt * 8;
        unsigned b[4][2];
#pragma unroll
        for (int nt = 0; nt < 4; nt++) {
            int n = nb + nt * 8 + gid;
            b[nt][0] = __float_as_uint(W[(k0 + tig) * SP + n]);
            b[nt][1] = __float_as_uint(W[(k0 + 4 + tig) * SP + n]);
        }
#pragma unroll
        for (int mt = 0; mt < 4; mt++) {
            int m = mt * 16;
            unsigned a0 = f2tf32(A[(m + gid) * SP + k0 + tig]);
            unsigned a1 = f2tf32(A[(m + gid + 8) * SP + k0 + tig]);
            unsigned a2 = f2tf32(A[(m + gid) * SP + k0 + tig + 4]);
            unsigned a3 = f2tf32(A[(m + gid + 8) * SP + k0 + tig + 4]);
#pragma unroll
            for (int nt = 0; nt < 4; nt++)
                mma_tf32(acc[mt][nt], a0, a1, a2, a3, b[nt][0], b[nt][1]);
        }
    }
    __syncthreads();  // everyone done reading sWg / sAe before overwrite

    // Exchange: gate->sigmoid into sSig(=sWg), res into sAe
    float* dstS = (w < 4) ? sWg : sAe;
    bool isGate = (w < 4);
#pragma unroll
    for (int mt = 0; mt < 4; mt++)
#pragma unroll
        for (int nt = 0; nt < 4; nt++) {
            int r0 = mt * 16 + gid;
            int c0 = nb + nt * 8 + 2 * tig;
            float v0 = acc[mt][nt][0], v1 = acc[mt][nt][1];
            float v2 = acc[mt][nt][2], v3 = acc[mt][nt][3];
            if (isGate) {
                v0 = sigmoidf_(v0); v1 = sigmoidf_(v1);
                v2 = sigmoidf_(v2); v3 = sigmoidf_(v3);
            }
            *(float2*)&dstS[r0 * SP + c0] = make_float2(v0, v1);
            *(float2*)&dstS[(r0 + 8) * SP + c0] = make_float2(v2, v3);
        }
    __syncthreads();

    // ---- Epilogue: out = h + sig * (res - h) ----
#pragma unroll
    for (int i = 0; i < 8; i++) {
        int row = w * 8 + i;
        float4 h4 = *(const float4*)&sAh[row * SP + col];
        float4 sg = *(const float4*)&sWg[row * SP + col];
        float4 rs = *(const float4*)&sAe[row * SP + col];
        float4 o;
        o.x = fmaf(sg.x, rs.x - h4.x, h4.x);
        o.y = fmaf(sg.y, rs.y - h4.y, h4.y);
        o.z = fmaf(sg.z, rs.z - h4.z, h4.z);
        o.w = fmaf(sg.w, rs.w - h4.w, h4.w);
        *(float4*)&out[(size_t)(base + row) * HH + col] = o;
    }
}

// ---------------------------------------------------------------------------
extern "C" void kernel_launch(void* const* d_in, const int* in_sizes, int n_in,
                              void* d_out, int out_size) {
    const float* pos_i     = (const float*)d_in[0];
    const float* pos_j     = (const float*)d_in[1];
    const float* hd_i      = (const float*)d_in[2];
    const float* hd_j      = (const float*)d_in[3];
    const int*   eidx      = (const int*)d_in[4];
    const float* edge_attr = (const float*)d_in[5];
    const float* embs_i    = (const float*)d_in[6];
    const float* embs_j    = (const float*)d_in[7];
    const float* Wgeo      = (const float*)d_in[8];
    const float* Wpair     = (const float*)d_in[9];
    const float* Wsem      = (const float*)d_in[10];
    const float* bsem      = (const float*)d_in[11];
    const float* gamma     = (const float*)d_in[12];
    const float* beta      = (const float*)d_in[13];
    const float* Wgate     = (const float*)d_in[14];
    const float* Wres      = (const float*)d_in[15];

    const int smem_pk   = (128 * SP * 2 + 64 * SP * 2) * 4;           // 202752
    const int smem_edge = (128 * SP * 2 + 64 * SP * 2 + 1280) * 4;    // 207872

    cudaFuncSetAttribute(pk_kernel, cudaFuncAttributeMaxDynamicSharedMemorySize,
                         smem_pk);
    cudaFuncSetAttribute(edge_kernel, cudaFuncAttributeMaxDynamicSharedMemorySize,
                         smem_edge);

    wcomb_kernel<<<10, 128>>>(Wgeo, Wpair);
    pk_kernel<<<(NN + 63) / 64, 256, smem_pk>>>(embs_i, embs_j, Wsem);
    edge_kernel<<<EE / 64, 256, smem_edge>>>(pos_i, pos_j, hd_i, hd_j, eidx,
                                             edge_attr, bsem, gamma, beta,
                                             Wgate, Wres, (float*)d_out);
}

// round 9
// speedup vs baseline: 3.0939x; 2.3312x over previous
#include <cuda_runtime.h>
#include <cuda_fp16.h>
#include <cstdint>
#include <cstring>
#include <math.h>

#define NN 50000
#define EE 600000
#define HH 128
#define SP 132          // pk kernel padded stride (floats)
#define NT 4688         // ceil(EE/128) edge tiles

// ---- gemm smem byte offsets ----
#define GOFF_WG   0          // 128*136 half = 34816
#define GOFF_WR   34816
#define GOFF_B0H  69632
#define GOFF_B0E  104448
#define GOFF_B1H  139264
#define GOFF_B1E  174080
#define GSMEM     208896

// Scratch (__device__ globals: alloc-free rule)
__device__ __align__(16) float  g_Pi[NN * HH];
__device__ __align__(16) float  g_Pj[NN * HH];
__device__ __align__(16) float  g_Wcomb[10 * HH];
__device__ __align__(16) float  g_H32[(size_t)EE * HH];
__device__ __align__(16) __half g_H16[(size_t)EE * HH];
__device__ __align__(16) __half g_EA16[(size_t)EE * HH];

__device__ __forceinline__ float sigmoidf_(float x) {
    return 1.0f / (1.0f + __expf(-x));
}
__device__ __forceinline__ uint32_t h2u(__half2 v) {
    uint32_t r;
    memcpy(&r, &v, 4);
    return r;
}
__device__ __forceinline__ unsigned f2tf32(float x) {
    unsigned r;
    asm("cvt.rna.tf32.f32 %0, %1;" : "=r"(r) : "f"(x));
    return r;
}
__device__ __forceinline__ uint32_t smem_u32(const void* smem_ptr) {
    uint32_t addr;
    asm("{ .reg .u64 tmp; cvta.to.shared.u64 tmp, %1; cvt.u32.u64 %0, tmp; }"
        : "=r"(addr) : "l"(smem_ptr));
    return addr;
}
__device__ __forceinline__ void mma_tf32(float* d, unsigned a0, unsigned a1,
                                         unsigned a2, unsigned a3,
                                         unsigned b0, unsigned b1) {
    asm volatile(
        "mma.sync.aligned.m16n8k8.row.col.f32.tf32.tf32.f32 "
        "{%0,%1,%2,%3}, {%4,%5,%6,%7}, {%8,%9}, {%0,%1,%2,%3};\n"
        : "+f"(d[0]), "+f"(d[1]), "+f"(d[2]), "+f"(d[3])
        : "r"(a0), "r"(a1), "r"(a2), "r"(a3), "r"(b0), "r"(b1));
}
__device__ __forceinline__ void mma_f16(float* d, uint32_t a0, uint32_t a1,
                                        uint32_t a2, uint32_t a3,
                                        uint32_t b0, uint32_t b1) {
    asm volatile(
        "mma.sync.aligned.m16n8k16.row.col.f32.f16.f16.f32 "
        "{%0,%1,%2,%3}, {%4,%5,%6,%7}, {%8,%9}, {%0,%1,%2,%3};\n"
        : "+f"(d[0]), "+f"(d[1]), "+f"(d[2]), "+f"(d[3])
        : "r"(a0), "r"(a1), "r"(a2), "r"(a3), "r"(b0), "r"(b1));
}

#define CP_ASYNC_16(dst_u32, src_ptr) \
    asm volatile("cp.async.cg.shared.global [%0], [%1], 16;" \
                 :: "r"(dst_u32), "l"(src_ptr) : "memory")
#define CP_COMMIT() asm volatile("cp.async.commit_group;" ::: "memory")
#define CP_WAIT(n)  asm volatile("cp.async.wait_group %0;" :: "n"(n) : "memory")

// ---------------------------------------------------------------------------
// Setup kernel: wcomb (blocks 0-9) + P precompute (tf32 mma, all blocks)
// ---------------------------------------------------------------------------
__global__ __launch_bounds__(256, 1) void pk_kernel(const float* __restrict__ Ei,
                                                    const float* __restrict__ Ej,
                                                    const float* __restrict__ Wsem,
                                                    const float* __restrict__ Wgeo,
                                                    const float* __restrict__ Wpair) {
    extern __shared__ float sm[];
    float* sWt = sm;
    float* sWb = sWt + 128 * SP;
    float* sAi = sWb + 128 * SP;
    float* sAj = sAi + 64 * SP;

    int tid = threadIdx.x;
    int lane = tid & 31;
    int w = tid >> 5;

    if (blockIdx.x < 10 && tid < 128) {
        int c = tid;
        int d = blockIdx.x;
        int dd = d % 5;
        const float* wp = Wpair + (d / 5) * 128 * HH;
        float acc = 0.0f;
#pragma unroll 16
        for (int m = 0; m < 128; m++)
            acc = fmaf(Wgeo[dd * HH + m], wp[m * HH + c], acc);
        g_Wcomb[d * HH + c] = acc;
    }

    for (int i = tid; i < 4096; i += 256) {
        int k = i >> 5, c4 = i & 31;
        float4 t = ((const float4*)Wsem)[i];
        float4 b = ((const float4*)(Wsem + 128 * HH))[i];
        *(uint4*)&sWt[k * SP + c4 * 4] =
            make_uint4(f2tf32(t.x), f2tf32(t.y), f2tf32(t.z), f2tf32(t.w));
        *(uint4*)&sWb[k * SP + c4 * 4] =
            make_uint4(f2tf32(b.x), f2tf32(b.y), f2tf32(b.z), f2tf32(b.w));
    }
    int base = blockIdx.x * 64;
    for (int i = tid; i < 2048; i += 256) {
        int r = i >> 5, c4 = i & 31;
        int row = base + r;
        float4 v = make_float4(0.f, 0.f, 0.f, 0.f);
        float4 u = make_float4(0.f, 0.f, 0.f, 0.f);
        if (row < NN) {
            v = ((const float4*)Ei)[row * 32 + c4];
            u = ((const float4*)Ej)[row * 32 + c4];
        }
        *(uint4*)&sAi[r * SP + c4 * 4] =
            make_uint4(f2tf32(v.x), f2tf32(v.y), f2tf32(v.z), f2tf32(v.w));
        *(uint4*)&sAj[r * SP + c4 * 4] =
            make_uint4(f2tf32(u.x), f2tf32(u.y), f2tf32(u.z), f2tf32(u.w));
    }
    __syncthreads();

    const float* A = (w < 4) ? sAi : sAj;
    const float* W = (w < 4) ? sWt : sWb;
    int nb = (w & 3) * 32;
    int gid = lane >> 2, tig = lane & 3;

    float acc[4][4][4];
#pragma unroll
    for (int mt = 0; mt < 4; mt++)
#pragma unroll
        for (int nt = 0; nt < 4; nt++)
#pragma unroll
            for (int q = 0; q < 4; q++) { acc[mt][nt][q] = 0.f; }

#pragma unroll
    for (int kt = 0; kt < 16; kt++) {
        int k0 = kt * 8;
        unsigned b[4][2];
#pragma unroll
        for (int nt = 0; nt < 4; nt++) {
            int n = nb + nt * 8 + gid;
            b[nt][0] = __float_as_uint(W[(k0 + tig) * SP + n]);
            b[nt][1] = __float_as_uint(W[(k0 + 4 + tig) * SP + n]);
        }
#pragma unroll
        for (int mt = 0; mt < 4; mt++) {
            int m = mt * 16;
            unsigned a0 = __float_as_uint(A[(m + gid) * SP + k0 + tig]);
            unsigned a1 = __float_as_uint(A[(m + gid + 8) * SP + k0 + tig]);
            unsigned a2 = __float_as_uint(A[(m + gid) * SP + k0 + tig + 4]);
            unsigned a3 = __float_as_uint(A[(m + gid + 8) * SP + k0 + tig + 4]);
#pragma unroll
            for (int nt = 0; nt < 4; nt++)
                mma_tf32(acc[mt][nt], a0, a1, a2, a3, b[nt][0], b[nt][1]);
        }
    }

    float* G = (w < 4) ? g_Pi : g_Pj;
#pragma unroll
    for (int mt = 0; mt < 4; mt++)
#pragma unroll
        for (int nt = 0; nt < 4; nt++) {
            int row0 = base + mt * 16 + gid;
            int col = nb + nt * 8 + 2 * tig;
            if (row0 < NN)
                *(float2*)&G[(size_t)row0 * HH + col] =
                    make_float2(acc[mt][nt][0], acc[mt][nt][1]);
            int row1 = row0 + 8;
            if (row1 < NN)
                *(float2*)&G[(size_t)row1 * HH + col] =
                    make_float2(acc[mt][nt][2], acc[mt][nt][3]);
        }
}

// ---------------------------------------------------------------------------
// Phase A kernel: geometry + gate + LayerNorm. 512 threads, 64 edges/CTA,
// one warp per edge (4 edges sequentially). High occupancy for latency hiding.
// Writes h fp32, h fp16, ea fp16 to global scratch.
// ---------------------------------------------------------------------------
__global__ __launch_bounds__(512, 2) void phaseA_kernel(
    const float* __restrict__ pos_i, const float* __restrict__ pos_j,
    const float* __restrict__ hd_i, const float* __restrict__ hd_j,
    const int* __restrict__ eidx, const float* __restrict__ edge_attr,
    const float* __restrict__ b_sem, const float* __restrict__ gamma,
    const float* __restrict__ beta) {
    __shared__ float sWc[10 * HH];

    int tid = threadIdx.x;
    int lane = tid & 31;
    int w = tid >> 5;
    int col = lane * 4;
    int base = blockIdx.x * 64;

    for (int i = tid; i < 1280; i += 512) sWc[i] = g_Wcomb[i];
    __syncthreads();

    float4 bs = *(const float4*)&b_sem[col];
    float4 gm = *(const float4*)&gamma[col];
    float4 bt = *(const float4*)&beta[col];

#pragma unroll 2
    for (int it = 0; it < 4; it++) {
        int e = base + w + 16 * it;
        int src = __ldg(&eidx[e]);
        int tgt = __ldg(&eidx[EE + e]);

        float2 pvi = __ldg(&((const float2*)pos_i)[src]);
        float2 pvj = __ldg(&((const float2*)pos_j)[tgt]);
        float ang_i = __ldg(&hd_i[src]);
        float ang_j = __ldg(&hd_j[tgt]);
        float dx = pvi.x - pvj.x;
        float dy = pvi.y - pvj.y;

        float sj, cj;
        __sincosf(ang_j, &sj, &cj);
        float x1 = dx * cj + dy * sj;
        float y1 = -dx * sj + dy * cj;
        float len1 = sqrtf(x1 * x1 + y1 * y1);
        float il1 = (len1 > 0.f) ? (1.f / len1) : 0.f;
        float ct1 = (len1 > 0.f) ? (x1 * il1) : 1.f;
        float st1 = y1 * il1;

        float si, ci;
        __sincosf(ang_i, &si, &ci);
        float x2 = -dx * ci - dy * si;
        float y2 = dx * si - dy * ci;
        float len2 = sqrtf(x2 * x2 + y2 * y2);
        float il2 = (len2 > 0.f) ? (1.f / len2) : 0.f;
        float ct2 = (len2 > 0.f) ? (x2 * il2) : 1.f;
        float st2 = y2 * il2;

        float shd, chd;
        __sincosf(ang_i - ang_j, &shd, &chd);

        float raw[10];
        raw[0] = len1; raw[1] = ct1; raw[2] = st1; raw[3] = chd; raw[4] = shd;
        raw[5] = len2; raw[6] = ct2; raw[7] = st2; raw[8] = chd; raw[9] = -shd;

        float4 g = make_float4(0.f, 0.f, 0.f, 0.f);
#pragma unroll
        for (int d = 0; d < 10; d++) {
            float4 wc = *(const float4*)&sWc[d * HH + col];
            g.x = fmaf(raw[d], wc.x, g.x);
            g.y = fmaf(raw[d], wc.y, g.y);
            g.z = fmaf(raw[d], wc.z, g.z);
            g.w = fmaf(raw[d], wc.w, g.w);
        }
        g.x = fmaxf(g.x, 0.f); g.y = fmaxf(g.y, 0.f);
        g.z = fmaxf(g.z, 0.f); g.w = fmaxf(g.w, 0.f);

        float4 Pi4 = __ldg((const float4*)&g_Pi[(size_t)src * HH + col]);
        float4 Pj4 = __ldg((const float4*)&g_Pj[(size_t)tgt * HH + col]);
        float4 ea4 = __ldg((const float4*)&edge_attr[(size_t)e * HH + col]);

        float4 pre;
        pre.x = fmaf(g.x, sigmoidf_(Pi4.x + Pj4.x + bs.x), ea4.x);
        pre.y = fmaf(g.y, sigmoidf_(Pi4.y + Pj4.y + bs.y), ea4.y);
        pre.z = fmaf(g.z, sigmoidf_(Pi4.z + Pj4.z + bs.z), ea4.z);
        pre.w = fmaf(g.w, sigmoidf_(Pi4.w + Pj4.w + bs.w), ea4.w);

        float ssum = pre.x + pre.y + pre.z + pre.w;
#pragma unroll
        for (int off = 16; off >= 1; off >>= 1)
            ssum += __shfl_xor_sync(0xffffffffu, ssum, off);
        float mu = ssum * (1.0f / 128.0f);
        float4 dv;
        dv.x = pre.x - mu; dv.y = pre.y - mu;
        dv.z = pre.z - mu; dv.w = pre.w - mu;
        float sq = dv.x * dv.x + dv.y * dv.y + dv.z * dv.z + dv.w * dv.w;
#pragma unroll
        for (int off = 16; off >= 1; off >>= 1)
            sq += __shfl_xor_sync(0xffffffffu, sq, off);
        float rstd = rsqrtf(sq * (1.0f / 128.0f) + 1e-5f);

        float4 h4;
        h4.x = fmaf(dv.x * rstd, gm.x, bt.x);
        h4.y = fmaf(dv.y * rstd, gm.y, bt.y);
        h4.z = fmaf(dv.z * rstd, gm.z, bt.z);
        h4.w = fmaf(dv.w * rstd, gm.w, bt.w);

        size_t o = (size_t)e * HH + col;
        *(float4*)&g_H32[o] = h4;

        __half2 hh0 = __float22half2_rn(make_float2(h4.x, h4.y));
        __half2 hh1 = __float22half2_rn(make_float2(h4.z, h4.w));
        *(uint2*)&g_H16[o] = make_uint2(h2u(hh0), h2u(hh1));

        __half2 ee0 = __float22half2_rn(make_float2(ea4.x, ea4.y));
        __half2 ee1 = __float22half2_rn(make_float2(ea4.z, ea4.w));
        *(uint2*)&g_EA16[o] = make_uint2(h2u(ee0), h2u(ee1));
    }
}

// ---------------------------------------------------------------------------
// GEMM kernel: persistent CTAs, 512 threads. Per tile (128 edges):
// gate = h @ Wgate, res = ea @ Wres via fp16 m16n8k16 mma; fused epilogue.
// Each warp owns a 32x32 output slab of BOTH GEMMs (fully local epilogue).
// A-tiles (h16, ea16) double-buffered via cp.async.
// ---------------------------------------------------------------------------
__global__ __launch_bounds__(512, 1) void gemm_kernel(
    const float* __restrict__ Wgate, const float* __restrict__ Wres,
    float* __restrict__ out) {
    extern __shared__ char smc[];
    __half* sWg = (__half*)(smc + GOFF_WG);
    __half* sWr = (__half*)(smc + GOFF_WR);
    uint32_t sb = smem_u32(smc);

    int tid = threadIdx.x;
    int lane = tid & 31;
    int w = tid >> 5;
    int gid = lane >> 2;
    int tig = lane & 3;
    int mb = (w >> 2) * 32;
    int nb = (w & 3) * 32;

    // stage weights once: sW[n][k] (transposed), stride 136 halves
    for (int i = tid; i < 16384; i += 512) {
        int n = i & 127, k = i >> 7;
        sWg[n * 136 + k] = __float2half(Wgate[k * HH + n]);
        sWr[n * 136 + k] = __float2half(Wres[k * HH + n]);
    }

    const uint32_t bufH[2] = {sb + GOFF_B0H, sb + GOFF_B1H};
    const uint32_t bufE[2] = {sb + GOFF_B0E, sb + GOFF_B1E};

    int t = blockIdx.x;
    if (t >= NT) return;

    // prologue: stage first tile
    for (int c = tid; c < 2048; c += 512) {
        int r = c >> 4, cc = c & 15;
        long e = (long)t * 128 + r;
        if (e >= EE) e = EE - 1;
        CP_ASYNC_16(bufH[0] + r * 272 + cc * 16, (const void*)(g_H16 + e * HH + cc * 8));
        CP_ASYNC_16(bufE[0] + r * 272 + cc * 16, (const void*)(g_EA16 + e * HH + cc * 8));
    }
    CP_COMMIT();

    int cur = 0;
    while (t < NT) {
        int nxt = t + (int)gridDim.x;
        if (nxt < NT) {
            for (int c = tid; c < 2048; c += 512) {
                int r = c >> 4, cc = c & 15;
                long e = (long)nxt * 128 + r;
                if (e >= EE) e = EE - 1;
                CP_ASYNC_16(bufH[cur ^ 1] + r * 272 + cc * 16,
                            (const void*)(g_H16 + e * HH + cc * 8));
                CP_ASYNC_16(bufE[cur ^ 1] + r * 272 + cc * 16,
                            (const void*)(g_EA16 + e * HH + cc * 8));
            }
            CP_COMMIT();
            CP_WAIT(1);
        } else {
            CP_WAIT(0);
        }
        __syncthreads();

        const __half* sH = (const __half*)(smc + (bufH[cur] - sb));
        const __half* sE = (const __half*)(smc + (bufE[cur] - sb));

        float aG[2][4][4];
        float aR[2][4][4];
#pragma unroll
        for (int mt = 0; mt < 2; mt++)
#pragma unroll
            for (int nt = 0; nt < 4; nt++)
#pragma unroll
                for (int q = 0; q < 4; q++) { aG[mt][nt][q] = 0.f; aR[mt][nt][q] = 0.f; }

#pragma unroll
        for (int kt = 0; kt < 8; kt++) {
            int k0 = kt * 16;
            uint32_t bg[4][2], br[4][2];
#pragma unroll
            for (int nt = 0; nt < 4; nt++) {
                int n = nb + nt * 8 + gid;
                bg[nt][0] = *(const uint32_t*)&sWg[n * 136 + k0 + 2 * tig];
                bg[nt][1] = *(const uint32_t*)&sWg[n * 136 + k0 + 2 * tig + 8];
                br[nt][0] = *(const uint32_t*)&sWr[n * 136 + k0 + 2 * tig];
                br[nt][1] = *(const uint32_t*)&sWr[n * 136 + k0 + 2 * tig + 8];
            }
#pragma unroll
            for (int mt = 0; mt < 2; mt++) {
                int r0 = mb + mt * 16 + gid;
                uint32_t ha0 = *(const uint32_t*)&sH[r0 * 136 + k0 + 2 * tig];
                uint32_t ha1 = *(const uint32_t*)&sH[(r0 + 8) * 136 + k0 + 2 * tig];
                uint32_t ha2 = *(const uint32_t*)&sH[r0 * 136 + k0 + 2 * tig + 8];
                uint32_t ha3 = *(const uint32_t*)&sH[(r0 + 8) * 136 + k0 + 2 * tig + 8];
                uint32_t ea0 = *(const uint32_t*)&sE[r0 * 136 + k0 + 2 * tig];
                uint32_t ea1 = *(const uint32_t*)&sE[(r0 + 8) * 136 + k0 + 2 * tig];
                uint32_t ea2 = *(const uint32_t*)&sE[r0 * 136 + k0 + 2 * tig + 8];
                uint32_t ea3 = *(const uint32_t*)&sE[(r0 + 8) * 136 + k0 + 2 * tig + 8];
#pragma unroll
                for (int nt = 0; nt < 4; nt++) {
                    mma_f16(aG[mt][nt], ha0, ha1, ha2, ha3, bg[nt][0], bg[nt][1]);
                    mma_f16(aR[mt][nt], ea0, ea1, ea2, ea3, br[nt][0], br[nt][1]);
                }
            }
        }

        // epilogue: out = h + sigmoid(gate) * (res - h), h exact fp32 from global
#pragma unroll
        for (int mt = 0; mt < 2; mt++) {
#pragma unroll
            for (int nt = 0; nt < 4; nt++) {
                int c0 = nb + nt * 8 + 2 * tig;
#pragma unroll
                for (int hf = 0; hf < 2; hf++) {
                    long e = (long)t * 128 + mb + mt * 16 + gid + hf * 8;
                    if (e < EE) {
                        float2 h2 = *(const float2*)&g_H32[(size_t)e * HH + c0];
                        float s0 = sigmoidf_(aG[mt][nt][hf * 2 + 0]);
                        float s1 = sigmoidf_(aG[mt][nt][hf * 2 + 1]);
                        float2 o;
                        o.x = fmaf(s0, aR[mt][nt][hf * 2 + 0] - h2.x, h2.x);
                        o.y = fmaf(s1, aR[mt][nt][hf * 2 + 1] - h2.y, h2.y);
                        *(float2*)&out[(size_t)e * HH + c0] = o;
                    }
                }
            }
        }
        __syncthreads();   // all warps done with buf[cur] before it is refilled
        cur ^= 1;
        t = nxt;
    }
}

// ---------------------------------------------------------------------------
extern "C" void kernel_launch(void* const* d_in, const int* in_sizes, int n_in,
                              void* d_out, int out_size) {
    const float* pos_i     = (const float*)d_in[0];
    const float* pos_j     = (const float*)d_in[1];
    const float* hd_i      = (const float*)d_in[2];
    const float* hd_j      = (const float*)d_in[3];
    const int*   eidx      = (const int*)d_in[4];
    const float* edge_attr = (const float*)d_in[5];
    const float* embs_i    = (const float*)d_in[6];
    const float* embs_j    = (const float*)d_in[7];
    const float* Wgeo      = (const float*)d_in[8];
    const float* Wpair     = (const float*)d_in[9];
    const float* Wsem      = (const float*)d_in[10];
    const float* bsem      = (const float*)d_in[11];
    const float* gamma     = (const float*)d_in[12];
    const float* beta      = (const float*)d_in[13];
    const float* Wgate     = (const float*)d_in[14];
    const float* Wres      = (const float*)d_in[15];

    const int smem_pk = (128 * SP * 2 + 64 * SP * 2) * 4;  // 202752

    cudaFuncSetAttribute(pk_kernel, cudaFuncAttributeMaxDynamicSharedMemorySize,
                         smem_pk);
    cudaFuncSetAttribute(gemm_kernel, cudaFuncAttributeMaxDynamicSharedMemorySize,
                         GSMEM);

    pk_kernel<<<(NN + 63) / 64, 256, smem_pk>>>(embs_i, embs_j, Wsem, Wgeo, Wpair);
    phaseA_kernel<<<EE / 64, 512>>>(pos_i, pos_j, hd_i, hd_j, eidx, edge_attr,
                                    bsem, gamma, beta);
    gemm_kernel<<<148, 512, GSMEM>>>(Wgate, Wres, (float*)d_out);
}

// round 10
// speedup vs baseline: 3.9841x; 1.2878x over previous
#include <cuda_runtime.h>
#include <cuda_fp16.h>
#include <cstdint>
#include <cstring>
#include <math.h>

#define NN 50000
#define EE 600000
#define HH 128
#define SP 132          // pk kernel padded stride (floats)
#define NPT 782         // ceil(NN/64) node tiles
#define NT 4688         // ceil(EE/128) edge tiles

// ---- gemm smem byte offsets ----
#define GOFF_WG   0          // 128*136 half = 34816
#define GOFF_WR   34816
#define GOFF_B0H  69632
#define GOFF_B0E  104448
#define GOFF_B1H  139264
#define GOFF_B1E  174080
#define GSMEM     208896

// Scratch (__device__ globals: alloc-free rule)
__device__ __align__(16) float  g_Pi[NN * HH];
__device__ __align__(16) float  g_Pj[NN * HH];
__device__ __align__(16) float  g_Wcomb[10 * HH];
__device__ __align__(16) __half g_H16[(size_t)EE * HH];
__device__ __align__(16) __half g_EA16[(size_t)EE * HH];

__device__ __forceinline__ float sigmoidf_(float x) {
    return 1.0f / (1.0f + __expf(-x));
}
__device__ __forceinline__ uint32_t h2u(__half2 v) {
    uint32_t r;
    memcpy(&r, &v, 4);
    return r;
}
__device__ __forceinline__ unsigned f2tf32(float x) {
    unsigned r;
    asm("cvt.rna.tf32.f32 %0, %1;" : "=r"(r) : "f"(x));
    return r;
}
__device__ __forceinline__ uint32_t smem_u32(const void* smem_ptr) {
    uint32_t addr;
    asm("{ .reg .u64 tmp; cvta.to.shared.u64 tmp, %1; cvt.u32.u64 %0, tmp; }"
        : "=r"(addr) : "l"(smem_ptr));
    return addr;
}
__device__ __forceinline__ void mma_tf32(float* d, unsigned a0, unsigned a1,
                                         unsigned a2, unsigned a3,
                                         unsigned b0, unsigned b1) {
    asm volatile(
        "mma.sync.aligned.m16n8k8.row.col.f32.tf32.tf32.f32 "
        "{%0,%1,%2,%3}, {%4,%5,%6,%7}, {%8,%9}, {%0,%1,%2,%3};\n"
        : "+f"(d[0]), "+f"(d[1]), "+f"(d[2]), "+f"(d[3])
        : "r"(a0), "r"(a1), "r"(a2), "r"(a3), "r"(b0), "r"(b1));
}
__device__ __forceinline__ void mma_f16(float* d, uint32_t a0, uint32_t a1,
                                        uint32_t a2, uint32_t a3,
                                        uint32_t b0, uint32_t b1) {
    asm volatile(
        "mma.sync.aligned.m16n8k16.row.col.f32.f16.f16.f32 "
        "{%0,%1,%2,%3}, {%4,%5,%6,%7}, {%8,%9}, {%0,%1,%2,%3};\n"
        : "+f"(d[0]), "+f"(d[1]), "+f"(d[2]), "+f"(d[3])
        : "r"(a0), "r"(a1), "r"(a2), "r"(a3), "r"(b0), "r"(b1));
}

#define CP_ASYNC_16(dst_u32, src_ptr) \
    asm volatile("cp.async.cg.shared.global [%0], [%1], 16;" \
                 :: "r"(dst_u32), "l"(src_ptr) : "memory")
#define CP_COMMIT() asm volatile("cp.async.commit_group;" ::: "memory")
#define CP_WAIT(n)  asm volatile("cp.async.wait_group %0;" :: "n"(n) : "memory")

// ---------------------------------------------------------------------------
// Setup kernel: wcomb (blocks 0-9) + P precompute (tf32 mma).
// PERSISTENT: 148 CTAs loop over node tiles; weights staged once per CTA.
// ---------------------------------------------------------------------------
__global__ __launch_bounds__(256, 1) void pk_kernel(const float* __restrict__ Ei,
                                                    const float* __restrict__ Ej,
                                                    const float* __restrict__ Wsem,
                                                    const float* __restrict__ Wgeo,
                                                    const float* __restrict__ Wpair) {
    extern __shared__ float sm[];
    float* sWt = sm;
    float* sWb = sWt + 128 * SP;
    float* sAi = sWb + 128 * SP;
    float* sAj = sAi + 64 * SP;

    int tid = threadIdx.x;
    int lane = tid & 31;
    int w = tid >> 5;

    if (blockIdx.x < 10 && tid < 128) {
        int c = tid;
        int d = blockIdx.x;
        int dd = d % 5;
        const float* wp = Wpair + (d / 5) * 128 * HH;
        float acc = 0.0f;
#pragma unroll 16
        for (int m = 0; m < 128; m++)
            acc = fmaf(Wgeo[dd * HH + m], wp[m * HH + c], acc);
        g_Wcomb[d * HH + c] = acc;
    }

    // stage weights once per CTA
    for (int i = tid; i < 4096; i += 256) {
        int k = i >> 5, c4 = i & 31;
        float4 t = ((const float4*)Wsem)[i];
        float4 b = ((const float4*)(Wsem + 128 * HH))[i];
        *(uint4*)&sWt[k * SP + c4 * 4] =
            make_uint4(f2tf32(t.x), f2tf32(t.y), f2tf32(t.z), f2tf32(t.w));
        *(uint4*)&sWb[k * SP + c4 * 4] =
            make_uint4(f2tf32(b.x), f2tf32(b.y), f2tf32(b.z), f2tf32(b.w));
    }

    const float* A = (w < 4) ? sAi : sAj;
    const float* W = (w < 4) ? sWt : sWb;
    int nb = (w & 3) * 32;
    int gid = lane >> 2, tig = lane & 3;

    for (int t = blockIdx.x; t < NPT; t += (int)gridDim.x) {
        int base = t * 64;
        __syncthreads();   // prior iteration's sA reads done before overwrite
        for (int i = tid; i < 2048; i += 256) {
            int r = i >> 5, c4 = i & 31;
            int row = base + r;
            float4 v = make_float4(0.f, 0.f, 0.f, 0.f);
            float4 u = make_float4(0.f, 0.f, 0.f, 0.f);
            if (row < NN) {
                v = ((const float4*)Ei)[row * 32 + c4];
                u = ((const float4*)Ej)[row * 32 + c4];
            }
            *(uint4*)&sAi[r * SP + c4 * 4] =
                make_uint4(f2tf32(v.x), f2tf32(v.y), f2tf32(v.z), f2tf32(v.w));
            *(uint4*)&sAj[r * SP + c4 * 4] =
                make_uint4(f2tf32(u.x), f2tf32(u.y), f2tf32(u.z), f2tf32(u.w));
        }
        __syncthreads();

        float acc[4][4][4];
#pragma unroll
        for (int mt = 0; mt < 4; mt++)
#pragma unroll
            for (int nt = 0; nt < 4; nt++)
#pragma unroll
                for (int q = 0; q < 4; q++) { acc[mt][nt][q] = 0.f; }

#pragma unroll
        for (int kt = 0; kt < 16; kt++) {
            int k0 = kt * 8;
            unsigned b[4][2];
#pragma unroll
            for (int nt = 0; nt < 4; nt++) {
                int n = nb + nt * 8 + gid;
                b[nt][0] = __float_as_uint(W[(k0 + tig) * SP + n]);
                b[nt][1] = __float_as_uint(W[(k0 + 4 + tig) * SP + n]);
            }
#pragma unroll
            for (int mt = 0; mt < 4; mt++) {
                int m = mt * 16;
                unsigned a0 = __float_as_uint(A[(m + gid) * SP + k0 + tig]);
                unsigned a1 = __float_as_uint(A[(m + gid + 8) * SP + k0 + tig]);
                unsigned a2 = __float_as_uint(A[(m + gid) * SP + k0 + tig + 4]);
                unsigned a3 = __float_as_uint(A[(m + gid + 8) * SP + k0 + tig + 4]);
#pragma unroll
                for (int nt = 0; nt < 4; nt++)
                    mma_tf32(acc[mt][nt], a0, a1, a2, a3, b[nt][0], b[nt][1]);
            }
        }

        float* G = (w < 4) ? g_Pi : g_Pj;
#pragma unroll
        for (int mt = 0; mt < 4; mt++)
#pragma unroll
            for (int nt = 0; nt < 4; nt++) {
                int row0 = base + mt * 16 + gid;
                int col = nb + nt * 8 + 2 * tig;
                if (row0 < NN)
                    *(float2*)&G[(size_t)row0 * HH + col] =
                        make_float2(acc[mt][nt][0], acc[mt][nt][1]);
                int row1 = row0 + 8;
                if (row1 < NN)
                    *(float2*)&G[(size_t)row1 * HH + col] =
                        make_float2(acc[mt][nt][2], acc[mt][nt][3]);
            }
    }
}

// ---------------------------------------------------------------------------
// Phase A kernel: geometry + gate + LayerNorm. 512 threads, 64 edges/CTA.
// Writes h fp16 and ea fp16 only (fp32 h round-trip eliminated).
// ---------------------------------------------------------------------------
__global__ __launch_bounds__(512, 2) void phaseA_kernel(
    const float* __restrict__ pos_i, const float* __restrict__ pos_j,
    const float* __restrict__ hd_i, const float* __restrict__ hd_j,
    const int* __restrict__ eidx, const float* __restrict__ edge_attr,
    const float* __restrict__ b_sem, const float* __restrict__ gamma,
    const float* __restrict__ beta) {
    __shared__ float sWc[10 * HH];

    int tid = threadIdx.x;
    int lane = tid & 31;
    int w = tid >> 5;
    int col = lane * 4;
    int base = blockIdx.x * 64;

    for (int i = tid; i < 1280; i += 512) sWc[i] = g_Wcomb[i];
    __syncthreads();

    float4 bs = *(const float4*)&b_sem[col];
    float4 gm = *(const float4*)&gamma[col];
    float4 bt = *(const float4*)&beta[col];

#pragma unroll 2
    for (int it = 0; it < 4; it++) {
        int e = base + w + 16 * it;
        int src = __ldg(&eidx[e]);
        int tgt = __ldg(&eidx[EE + e]);

        float2 pvi = __ldg(&((const float2*)pos_i)[src]);
        float2 pvj = __ldg(&((const float2*)pos_j)[tgt]);
        float ang_i = __ldg(&hd_i[src]);
        float ang_j = __ldg(&hd_j[tgt]);
        float dx = pvi.x - pvj.x;
        float dy = pvi.y - pvj.y;

        float sj, cj;
        __sincosf(ang_j, &sj, &cj);
        float x1 = dx * cj + dy * sj;
        float y1 = -dx * sj + dy * cj;
        float len1 = sqrtf(x1 * x1 + y1 * y1);
        float il1 = (len1 > 0.f) ? (1.f / len1) : 0.f;
        float ct1 = (len1 > 0.f) ? (x1 * il1) : 1.f;
        float st1 = y1 * il1;

        float si, ci;
        __sincosf(ang_i, &si, &ci);
        float x2 = -dx * ci - dy * si;
        float y2 = dx * si - dy * ci;
        float len2 = sqrtf(x2 * x2 + y2 * y2);
        float il2 = (len2 > 0.f) ? (1.f / len2) : 0.f;
        float ct2 = (len2 > 0.f) ? (x2 * il2) : 1.f;
        float st2 = y2 * il2;

        float shd, chd;
        __sincosf(ang_i - ang_j, &shd, &chd);

        float raw[10];
        raw[0] = len1; raw[1] = ct1; raw[2] = st1; raw[3] = chd; raw[4] = shd;
        raw[5] = len2; raw[6] = ct2; raw[7] = st2; raw[8] = chd; raw[9] = -shd;

        float4 g = make_float4(0.f, 0.f, 0.f, 0.f);
#pragma unroll
        for (int d = 0; d < 10; d++) {
            float4 wc = *(const float4*)&sWc[d * HH + col];
            g.x = fmaf(raw[d], wc.x, g.x);
            g.y = fmaf(raw[d], wc.y, g.y);
            g.z = fmaf(raw[d], wc.z, g.z);
            g.w = fmaf(raw[d], wc.w, g.w);
        }
        g.x = fmaxf(g.x, 0.f); g.y = fmaxf(g.y, 0.f);
        g.z = fmaxf(g.z, 0.f); g.w = fmaxf(g.w, 0.f);

        float4 Pi4 = __ldg((const float4*)&g_Pi[(size_t)src * HH + col]);
        float4 Pj4 = __ldg((const float4*)&g_Pj[(size_t)tgt * HH + col]);
        float4 ea4 = __ldg((const float4*)&edge_attr[(size_t)e * HH + col]);

        float4 pre;
        pre.x = fmaf(g.x, sigmoidf_(Pi4.x + Pj4.x + bs.x), ea4.x);
        pre.y = fmaf(g.y, sigmoidf_(Pi4.y + Pj4.y + bs.y), ea4.y);
        pre.z = fmaf(g.z, sigmoidf_(Pi4.z + Pj4.z + bs.z), ea4.z);
        pre.w = fmaf(g.w, sigmoidf_(Pi4.w + Pj4.w + bs.w), ea4.w);

        float ssum = pre.x + pre.y + pre.z + pre.w;
#pragma unroll
        for (int off = 16; off >= 1; off >>= 1)
            ssum += __shfl_xor_sync(0xffffffffu, ssum, off);
        float mu = ssum * (1.0f / 128.0f);
        float4 dv;
        dv.x = pre.x - mu; dv.y = pre.y - mu;
        dv.z = pre.z - mu; dv.w = pre.w - mu;
        float sq = dv.x * dv.x + dv.y * dv.y + dv.z * dv.z + dv.w * dv.w;
#pragma unroll
        for (int off = 16; off >= 1; off >>= 1)
            sq += __shfl_xor_sync(0xffffffffu, sq, off);
        float rstd = rsqrtf(sq * (1.0f / 128.0f) + 1e-5f);

        float4 h4;
        h4.x = fmaf(dv.x * rstd, gm.x, bt.x);
        h4.y = fmaf(dv.y * rstd, gm.y, bt.y);
        h4.z = fmaf(dv.z * rstd, gm.z, bt.z);
        h4.w = fmaf(dv.w * rstd, gm.w, bt.w);

        size_t o = (size_t)e * HH + col;
        __half2 hh0 = __float22half2_rn(make_float2(h4.x, h4.y));
        __half2 hh1 = __float22half2_rn(make_float2(h4.z, h4.w));
        *(uint2*)&g_H16[o] = make_uint2(h2u(hh0), h2u(hh1));

        __half2 ee0 = __float22half2_rn(make_float2(ea4.x, ea4.y));
        __half2 ee1 = __float22half2_rn(make_float2(ea4.z, ea4.w));
        *(uint2*)&g_EA16[o] = make_uint2(h2u(ee0), h2u(ee1));
    }
}

// ---------------------------------------------------------------------------
// GEMM kernel: persistent CTAs, 512 threads. Per tile (128 edges):
// gate = h @ Wgate, res = ea @ Wres via fp16 m16n8k16 mma; fused epilogue.
// Epilogue h comes from the smem fp16 tile (no fp32 global round-trip).
// ---------------------------------------------------------------------------
__global__ __launch_bounds__(512, 1) void gemm_kernel(
    const float* __restrict__ Wgate, const float* __restrict__ Wres,
    float* __restrict__ out) {
    extern __shared__ char smc[];
    __half* sWg = (__half*)(smc + GOFF_WG);
    __half* sWr = (__half*)(smc + GOFF_WR);
    uint32_t sb = smem_u32(smc);

    int tid = threadIdx.x;
    int lane = tid & 31;
    int w = tid >> 5;
    int gid = lane >> 2;
    int tig = lane & 3;
    int mb = (w >> 2) * 32;
    int nb = (w & 3) * 32;

    // stage weights once: sW[n][k] (transposed), stride 136 halves
    for (int i = tid; i < 16384; i += 512) {
        int n = i & 127, k = i >> 7;
        sWg[n * 136 + k] = __float2half(Wgate[k * HH + n]);
        sWr[n * 136 + k] = __float2half(Wres[k * HH + n]);
    }

    const uint32_t bufH[2] = {sb + GOFF_B0H, sb + GOFF_B1H};
    const uint32_t bufE[2] = {sb + GOFF_B0E, sb + GOFF_B1E};

    int t = blockIdx.x;
    if (t >= NT) return;

    // prologue: stage first tile
    for (int c = tid; c < 2048; c += 512) {
        int r = c >> 4, cc = c & 15;
        long e = (long)t * 128 + r;
        if (e >= EE) e = EE - 1;
        CP_ASYNC_16(bufH[0] + r * 272 + cc * 16, (const void*)(g_H16 + e * HH + cc * 8));
        CP_ASYNC_16(bufE[0] + r * 272 + cc * 16, (const void*)(g_EA16 + e * HH + cc * 8));
    }
    CP_COMMIT();

    int cur = 0;
    while (t < NT) {
        int nxt = t + (int)gridDim.x;
        if (nxt < NT) {
            for (int c = tid; c < 2048; c += 512) {
                int r = c >> 4, cc = c & 15;
                long e = (long)nxt * 128 + r;
                if (e >= EE) e = EE - 1;
                CP_ASYNC_16(bufH[cur ^ 1] + r * 272 + cc * 16,
                            (const void*)(g_H16 + e * HH + cc * 8));
                CP_ASYNC_16(bufE[cur ^ 1] + r * 272 + cc * 16,
                            (const void*)(g_EA16 + e * HH + cc * 8));
            }
            CP_COMMIT();
            CP_WAIT(1);
        } else {
            CP_WAIT(0);
        }
        __syncthreads();

        const __half* sH = (const __half*)(smc + (bufH[cur] - sb));
        const __half* sE = (const __half*)(smc + (bufE[cur] - sb));

        float aG[2][4][4];
        float aR[2][4][4];
#pragma unroll
        for (int mt = 0; mt < 2; mt++)
#pragma unroll
            for (int nt = 0; nt < 4; nt++)
#pragma unroll
                for (int q = 0; q < 4; q++) { aG[mt][nt][q] = 0.f; aR[mt][nt][q] = 0.f; }

#pragma unroll
        for (int kt = 0; kt < 8; kt++) {
            int k0 = kt * 16;
            uint32_t bg[4][2], br[4][2];
#pragma unroll
            for (int nt = 0; nt < 4; nt++) {
                int n = nb + nt * 8 + gid;
                bg[nt][0] = *(const uint32_t*)&sWg[n * 136 + k0 + 2 * tig];
                bg[nt][1] = *(const uint32_t*)&sWg[n * 136 + k0 + 2 * tig + 8];
                br[nt][0] = *(const uint32_t*)&sWr[n * 136 + k0 + 2 * tig];
                br[nt][1] = *(const uint32_t*)&sWr[n * 136 + k0 + 2 * tig + 8];
            }
#pragma unroll
            for (int mt = 0; mt < 2; mt++) {
                int r0 = mb + mt * 16 + gid;
                uint32_t ha0 = *(const uint32_t*)&sH[r0 * 136 + k0 + 2 * tig];
                uint32_t ha1 = *(const uint32_t*)&sH[(r0 + 8) * 136 + k0 + 2 * tig];
                uint32_t ha2 = *(const uint32_t*)&sH[r0 * 136 + k0 + 2 * tig + 8];
                uint32_t ha3 = *(const uint32_t*)&sH[(r0 + 8) * 136 + k0 + 2 * tig + 8];
                uint32_t ea0 = *(const uint32_t*)&sE[r0 * 136 + k0 + 2 * tig];
                uint32_t ea1 = *(const uint32_t*)&sE[(r0 + 8) * 136 + k0 + 2 * tig];
                uint32_t ea2 = *(const uint32_t*)&sE[r0 * 136 + k0 + 2 * tig + 8];
                uint32_t ea3 = *(const uint32_t*)&sE[(r0 + 8) * 136 + k0 + 2 * tig + 8];
#pragma unroll
                for (int nt = 0; nt < 4; nt++) {
                    mma_f16(aG[mt][nt], ha0, ha1, ha2, ha3, bg[nt][0], bg[nt][1]);
                    mma_f16(aR[mt][nt], ea0, ea1, ea2, ea3, br[nt][0], br[nt][1]);
                }
            }
        }

        // epilogue: out = h + sigmoid(gate) * (res - h), h from smem fp16 tile
#pragma unroll
        for (int mt = 0; mt < 2; mt++) {
#pragma unroll
            for (int nt = 0; nt < 4; nt++) {
                int c0 = nb + nt * 8 + 2 * tig;
#pragma unroll
                for (int hf = 0; hf < 2; hf++) {
                    int r = mb + mt * 16 + gid + hf * 8;
                    long e = (long)t * 128 + r;
                    if (e < EE) {
                        float2 h2 = __half22float2(*(const __half2*)&sH[r * 136 + c0]);
                        float s0 = sigmoidf_(aG[mt][nt][hf * 2 + 0]);
                        float s1 = sigmoidf_(aG[mt][nt][hf * 2 + 1]);
                        float2 o;
                        o.x = fmaf(s0, aR[mt][nt][hf * 2 + 0] - h2.x, h2.x);
                        o.y = fmaf(s1, aR[mt][nt][hf * 2 + 1] - h2.y, h2.y);
                        *(float2*)&out[(size_t)e * HH + c0] = o;
                    }
                }
            }
        }
        __syncthreads();   // all warps done with buf[cur] before it is refilled
        cur ^= 1;
        t = nxt;
    }
}

// ---------------------------------------------------------------------------
extern "C" void kernel_launch(void* const* d_in, const int* in_sizes, int n_in,
                              void* d_out, int out_size) {
    const float* pos_i     = (const float*)d_in[0];
    const float* pos_j     = (const float*)d_in[1];
    const float* hd_i      = (const float*)d_in[2];
    const float* hd_j      = (const float*)d_in[3];
    const int*   eidx      = (const int*)d_in[4];
    const float* edge_attr = (const float*)d_in[5];
    const float* embs_i    = (const float*)d_in[6];
    const float* embs_j    = (const float*)d_in[7];
    const float* Wgeo      = (const float*)d_in[8];
    const float* Wpair     = (const float*)d_in[9];
    const float* Wsem      = (const float*)d_in[10];
    const float* bsem      = (const float*)d_in[11];
    const float* gamma     = (const float*)d_in[12];
    const float* beta      = (const float*)d_in[13];
    const float* Wgate     = (const float*)d_in[14];
    const float* Wres      = (const float*)d_in[15];

    const int smem_pk = (128 * SP * 2 + 64 * SP * 2) * 4;  // 202752

    cudaFuncSetAttribute(pk_kernel, cudaFuncAttributeMaxDynamicSharedMemorySize,
                         smem_pk);
    cudaFuncSetAttribute(gemm_kernel, cudaFuncAttributeMaxDynamicSharedMemorySize,
                         GSMEM);

    pk_kernel<<<148, 256, smem_pk>>>(embs_i, embs_j, Wsem, Wgeo, Wpair);
    phaseA_kernel<<<EE / 64, 512>>>(pos_i, pos_j, hd_i, hd_j, eidx, edge_attr,
                                    bsem, gamma, beta);
    gemm_kernel<<<148, 512, GSMEM>>>(Wgate, Wres, (float*)d_out);
}